// round 3
// baseline (speedup 1.0000x reference)
#include <cuda_runtime.h>
#include <cuda_bf16.h>

// ---------------- Problem constants ----------------
#define BATCH     2
#define SEQLEN    1024
#define TOK       (BATCH*SEQLEN)        // 2048
#define D_MODEL   1024
#define D_INNER   2048
#define NHEADS    32
#define HEADDIM   64
#define D_STATE   128
#define D_CONV    4
#define CONV_DIM  (D_INNER + 2*D_STATE)         // 2304
#define D_IN_PROJ (2*D_INNER + 2*D_STATE + NHEADS) // 4384
#define INTER     2752
#define EPS       1e-6f

// ---------------- Scratch (device globals; no dynamic alloc allowed) ----------------
__device__ float g_h     [TOK * D_MODEL];     // rmsnorm(hidden)
__device__ float g_zx    [TOK * D_IN_PROJ];   // in_proj output
__device__ float g_xbc   [TOK * CONV_DIM];    // conv+silu output
__device__ float g_dt    [TOK * NHEADS];      // softplus dt
__device__ float g_y     [TOK * D_INNER];     // scan output (+ D*x)
__device__ float g_yn    [TOK * D_INNER];     // gated rmsnorm output
__device__ float g_x1    [TOK * D_MODEL];     // residual after out_proj
__device__ float g_h2    [TOK * D_MODEL];     // post-norm
__device__ float g_gate  [TOK * INTER];
__device__ float g_up    [TOK * INTER];
__device__ float g_inter [TOK * INTER];

// ---------------- RMSNorm ----------------
__global__ void rmsnorm_kernel(const float* __restrict__ x, const float* __restrict__ w,
                               float* __restrict__ o, int cols) {
    int row = blockIdx.x;
    const float* xr = x + (long)row * cols;
    float*       orr = o + (long)row * cols;
    float s = 0.f;
    for (int c = threadIdx.x; c < cols; c += blockDim.x) { float v = xr[c]; s += v * v; }
    __shared__ float red[256];
    red[threadIdx.x] = s; __syncthreads();
    for (int st = 128; st > 0; st >>= 1) {
        if (threadIdx.x < st) red[threadIdx.x] += red[threadIdx.x + st];
        __syncthreads();
    }
    float scale = rsqrtf(red[0] / (float)cols + EPS);
    for (int c = threadIdx.x; c < cols; c += blockDim.x) orr[c] = xr[c] * scale * w[c];
}

// ---------------- Generic SGEMM: C[M,N] = A[M,K] * B[N,K]^T (+ res) ----------------
__global__ void gemm_nt(const float* __restrict__ A, const float* __restrict__ B,
                        const float* __restrict__ res, float* __restrict__ C,
                        int M, int N, int K) {
    const int BM = 64, BN = 64, BK = 16;
    __shared__ float As[BK][BM + 1];
    __shared__ float Bs[BK][BN + 1];
    int tid = threadIdx.x;           // 256 threads
    int tx = tid & 15, ty = tid >> 4;
    int m0 = blockIdx.y * BM, n0 = blockIdx.x * BN;
    float acc[4][4];
#pragma unroll
    for (int i = 0; i < 4; i++)
#pragma unroll
        for (int j = 0; j < 4; j++) acc[i][j] = 0.f;

    int ak = tid & 15;   // k within tile
    int ar = tid >> 4;   // row base (0..15), step 16

    for (int k0 = 0; k0 < K; k0 += BK) {
#pragma unroll
        for (int i = 0; i < 4; i++) {
            int m = ar + i * 16;
            int gm = m0 + m, gk = k0 + ak;
            As[ak][m] = (gm < M && gk < K) ? A[(long)gm * K + gk] : 0.f;
            int gn = n0 + m;
            Bs[ak][m] = (gn < N && gk < K) ? B[(long)gn * K + gk] : 0.f;
        }
        __syncthreads();
#pragma unroll
        for (int k = 0; k < BK; k++) {
            float af[4], bf[4];
#pragma unroll
            for (int i = 0; i < 4; i++) af[i] = As[k][ty * 4 + i];
#pragma unroll
            for (int j = 0; j < 4; j++) bf[j] = Bs[k][tx * 4 + j];
#pragma unroll
            for (int i = 0; i < 4; i++)
#pragma unroll
                for (int j = 0; j < 4; j++) acc[i][j] += af[i] * bf[j];
        }
        __syncthreads();
    }
#pragma unroll
    for (int i = 0; i < 4; i++) {
        int m = m0 + ty * 4 + i;
        if (m >= M) continue;
#pragma unroll
        for (int j = 0; j < 4; j++) {
            int n = n0 + tx * 4 + j;
            if (n >= N) continue;
            float v = acc[i][j];
            if (res) v += res[(long)m * N + n];
            C[(long)m * N + n] = v;
        }
    }
}

// ---------------- Causal depthwise conv (width 4) + SiLU ----------------
__global__ void conv_silu_kernel(const float* __restrict__ zx,
                                 const float* __restrict__ cw,
                                 const float* __restrict__ cb,
                                 float* __restrict__ xbc) {
    long idx = (long)blockIdx.x * blockDim.x + threadIdx.x;
    if (idx >= (long)TOK * CONV_DIM) return;
    int c = (int)(idx % CONV_DIM);
    int row = (int)(idx / CONV_DIM);
    int l = row & (SEQLEN - 1);
    int b = row >> 10;               // SEQLEN = 1024
    float v = cb[c];
#pragma unroll
    for (int k = 0; k < D_CONV; k++) {
        int li = l - (D_CONV - 1) + k;
        if (li >= 0)
            v += zx[((long)(b * SEQLEN + li)) * D_IN_PROJ + D_INNER + c] * cw[c * D_CONV + k];
    }
    xbc[idx] = v / (1.f + expf(-v));
}

// ---------------- dt softplus ----------------
__global__ void dt_softplus_kernel(const float* __restrict__ zx,
                                   const float* __restrict__ dt_bias,
                                   float* __restrict__ dtb) {
    int idx = blockIdx.x * blockDim.x + threadIdx.x;
    if (idx >= TOK * NHEADS) return;
    int h = idx & (NHEADS - 1);
    int row = idx >> 5;
    float x = zx[(long)row * D_IN_PROJ + (D_IN_PROJ - NHEADS) + h] + dt_bias[h];
    dtb[idx] = (x > 20.f) ? x : log1pf(expf(x));
}

// ---------------- SSM selective scan: one CTA per (batch, head) ----------------
__global__ void scan_kernel(const float* __restrict__ xbc,
                            const float* __restrict__ dtb,
                            const float* __restrict__ A_log,
                            const float* __restrict__ Dp,
                            float* __restrict__ y) {
    int b  = blockIdx.x >> 5;        // /32
    int hh = blockIdx.x & 31;
    int tid = threadIdx.x;           // 128
    int p = tid >> 1;                // 0..63
    int nb = (tid & 1) * 64;         // n-half base
    float A  = -expf(A_log[hh]);
    float Dh = Dp[hh];

    float hst[64];
#pragma unroll
    for (int i = 0; i < 64; i++) hst[i] = 0.f;

    __shared__ float Bs[128], Cs[128], xs[64];
    __shared__ float sdt;

    for (int t = 0; t < SEQLEN; t++) {
        int row = b * SEQLEN + t;
        const float* base = xbc + (long)row * CONV_DIM;
        __syncthreads();
        Bs[tid] = base[D_INNER + tid];
        Cs[tid] = base[D_INNER + D_STATE + tid];
        if (tid < 64) xs[tid] = base[hh * HEADDIM + tid];
        if (tid == 0) sdt = dtb[row * NHEADS + hh];
        __syncthreads();

        float dt   = sdt;
        float dA   = expf(dt * A);
        float xp   = xs[p];
        float coef = dt * xp;
        float acc  = 0.f;
#pragma unroll
        for (int i = 0; i < 64; i++) {
            hst[i] = hst[i] * dA + coef * Bs[nb + i];
            acc   += hst[i] * Cs[nb + i];
        }
        acc += __shfl_xor_sync(0xffffffffu, acc, 1);
        if ((tid & 1) == 0)
            y[(long)row * D_INNER + hh * HEADDIM + p] = acc + Dh * xp;
    }
}

// ---------------- Gated RMSNorm: rmsnorm(y * silu(z)) * w ----------------
__global__ void gated_rmsnorm_kernel(const float* __restrict__ y,
                                     const float* __restrict__ zx,
                                     const float* __restrict__ w,
                                     float* __restrict__ o) {
    int row = blockIdx.x;
    const float* yr = y  + (long)row * D_INNER;
    const float* zr = zx + (long)row * D_IN_PROJ;   // z = first D_INNER cols
    float*       orr = o + (long)row * D_INNER;
    __shared__ float vbuf[D_INNER];
    __shared__ float red[256];
    float s = 0.f;
    for (int c = threadIdx.x; c < D_INNER; c += blockDim.x) {
        float z = zr[c];
        float v = yr[c] * (z / (1.f + expf(-z)));
        vbuf[c] = v;
        s += v * v;
    }
    red[threadIdx.x] = s; __syncthreads();
    for (int st = 128; st > 0; st >>= 1) {
        if (threadIdx.x < st) red[threadIdx.x] += red[threadIdx.x + st];
        __syncthreads();
    }
    float scale = rsqrtf(red[0] / (float)D_INNER + EPS);
    for (int c = threadIdx.x; c < D_INNER; c += blockDim.x)
        orr[c] = vbuf[c] * scale * w[c];
}

// ---------------- SwiGLU combine ----------------
__global__ void swiglu_kernel(const float* __restrict__ g, const float* __restrict__ u,
                              float* __restrict__ o) {
    long idx = (long)blockIdx.x * blockDim.x + threadIdx.x;
    if (idx >= (long)TOK * INTER) return;
    float gv = g[idx];
    o[idx] = (gv / (1.f + expf(-gv))) * u[idx];
}

// ---------------- Launch ----------------
extern "C" void kernel_launch(void* const* d_in, const int* in_sizes, int n_in,
                              void* d_out, int out_size) {
    const float* hidden     = (const float*)d_in[0];
    const float* norm_w     = (const float*)d_in[1];
    const float* in_proj_w  = (const float*)d_in[2];
    const float* conv_w     = (const float*)d_in[3];
    const float* conv_b     = (const float*)d_in[4];
    const float* dt_bias    = (const float*)d_in[5];
    const float* A_log      = (const float*)d_in[6];
    const float* Dp         = (const float*)d_in[7];
    const float* ssm_norm_w = (const float*)d_in[8];
    const float* out_proj_w = (const float*)d_in[9];
    const float* post_norm_w= (const float*)d_in[10];
    const float* gate_w     = (const float*)d_in[11];
    const float* up_w       = (const float*)d_in[12];
    const float* down_w     = (const float*)d_in[13];
    float* out = (float*)d_out;

    float *h, *zx, *xbc, *dtb, *y, *yn, *x1, *h2, *gt, *up, *it;
    cudaGetSymbolAddress((void**)&h,   g_h);
    cudaGetSymbolAddress((void**)&zx,  g_zx);
    cudaGetSymbolAddress((void**)&xbc, g_xbc);
    cudaGetSymbolAddress((void**)&dtb, g_dt);
    cudaGetSymbolAddress((void**)&y,   g_y);
    cudaGetSymbolAddress((void**)&yn,  g_yn);
    cudaGetSymbolAddress((void**)&x1,  g_x1);
    cudaGetSymbolAddress((void**)&h2,  g_h2);
    cudaGetSymbolAddress((void**)&gt,  g_gate);
    cudaGetSymbolAddress((void**)&up,  g_up);
    cudaGetSymbolAddress((void**)&it,  g_inter);

    // 1) pre-norm
    rmsnorm_kernel<<<TOK, 256>>>(hidden, norm_w, h, D_MODEL);

    // 2) in_proj: zx[TOK, 4384] = h @ in_proj_w^T
    {
        dim3 grid((D_IN_PROJ + 63) / 64, (TOK + 63) / 64);
        gemm_nt<<<grid, 256>>>(h, in_proj_w, nullptr, zx, TOK, D_IN_PROJ, D_MODEL);
    }

    // 3) causal conv + silu
    {
        long total = (long)TOK * CONV_DIM;
        conv_silu_kernel<<<(unsigned)((total + 255) / 256), 256>>>(zx, conv_w, conv_b, xbc);
    }

    // 4) dt softplus
    dt_softplus_kernel<<<(TOK * NHEADS + 255) / 256, 256>>>(zx, dt_bias, dtb);

    // 5) SSM scan
    scan_kernel<<<BATCH * NHEADS, 128>>>(xbc, dtb, A_log, Dp, y);

    // 6) gated rmsnorm
    gated_rmsnorm_kernel<<<TOK, 256>>>(y, zx, ssm_norm_w, yn);

    // 7) out_proj + residual
    {
        dim3 grid((D_MODEL + 63) / 64, (TOK + 63) / 64);
        gemm_nt<<<grid, 256>>>(yn, out_proj_w, hidden, x1, TOK, D_MODEL, D_INNER);
    }

    // 8) post-norm
    rmsnorm_kernel<<<TOK, 256>>>(x1, post_norm_w, h2, D_MODEL);

    // 9) gate & up GEMMs
    {
        dim3 grid((INTER + 63) / 64, (TOK + 63) / 64);
        gemm_nt<<<grid, 256>>>(h2, gate_w, nullptr, gt, TOK, INTER, D_MODEL);
        gemm_nt<<<grid, 256>>>(h2, up_w,   nullptr, up, TOK, INTER, D_MODEL);
    }

    // 10) swiglu
    {
        long total = (long)TOK * INTER;
        swiglu_kernel<<<(unsigned)((total + 255) / 256), 256>>>(gt, up, it);
    }

    // 11) down proj + residual -> out
    {
        dim3 grid((D_MODEL + 63) / 64, (TOK + 63) / 64);
        gemm_nt<<<grid, 256>>>(it, down_w, x1, out, TOK, D_MODEL, INTER);
    }
}

// round 7
// speedup vs baseline: 1.8852x; 1.8852x over previous
#include <cuda_runtime.h>
#include <cuda_bf16.h>
#include <mma.h>

using namespace nvcuda;

// ---------------- Problem constants ----------------
#define BATCH     2
#define SEQLEN    1024
#define TOK       (BATCH*SEQLEN)        // 2048
#define D_MODEL   1024
#define D_INNER   2048
#define NHEADS    32
#define HEADDIM   64
#define D_STATE   128
#define D_CONV    4
#define CONV_DIM  (D_INNER + 2*D_STATE)            // 2304
#define D_IN_PROJ (2*D_INNER + 2*D_STATE + NHEADS) // 4384
#define INTER     2752
#define EPS       1e-6f

// ---------------- Scratch (device globals) ----------------
__device__ float g_h     [TOK * D_MODEL];
__device__ float g_zx    [TOK * D_IN_PROJ];
__device__ float g_xbc   [TOK * CONV_DIM];
__device__ float g_dt    [TOK * NHEADS];
__device__ float g_y     [TOK * D_INNER];
__device__ float g_yn    [TOK * D_INNER];
__device__ float g_x1    [TOK * D_MODEL];
__device__ float g_h2    [TOK * D_MODEL];
__device__ float g_gate  [TOK * INTER];
__device__ float g_up    [TOK * INTER];
__device__ float g_inter [TOK * INTER];

// ---------------- RMSNorm ----------------
__global__ void rmsnorm_kernel(const float* __restrict__ x, const float* __restrict__ w,
                               float* __restrict__ o, int cols) {
    int row = blockIdx.x;
    const float* xr = x + (long)row * cols;
    float*       orr = o + (long)row * cols;
    float s = 0.f;
    for (int c = threadIdx.x; c < cols; c += blockDim.x) { float v = xr[c]; s += v * v; }
    __shared__ float red[256];
    red[threadIdx.x] = s; __syncthreads();
    for (int st = 128; st > 0; st >>= 1) {
        if (threadIdx.x < st) red[threadIdx.x] += red[threadIdx.x + st];
        __syncthreads();
    }
    float scale = rsqrtf(red[0] / (float)cols + EPS);
    for (int c = threadIdx.x; c < cols; c += blockDim.x) orr[c] = xr[c] * scale * w[c];
}

// ---------------- TF32 tensor-core GEMM: C[M,N] = A[M,K] @ B[N,K]^T (+ res) ----------
// CTA tile 128x64, BK=16, 256 threads = 8 warps (4 along M x 2 along N), warp 32x32.
// Requires: M % 128 == 0, K % 16 == 0. N handled with guards.
#define GBM 128
#define GBN 64
#define GBK 16
#define GPAD 24   // smem row stride (floats): mult of 4, rows 16B-aligned

__global__ __launch_bounds__(256, 2)
void gemm_tf32(const float* __restrict__ A, const float* __restrict__ B,
               const float* __restrict__ res, float* __restrict__ C,
               int M, int N, int K) {
    __shared__ __align__(32) float sm[9216];           // 36864 B
    float* As = sm;                 // [2][128][GPAD]
    float* Bs = sm + 2 * GBM * GPAD;// [2][ 64][GPAD]

    int tid = threadIdx.x;
    int wid = tid >> 5;
    int wm  = wid >> 1;             // 0..3
    int wn  = wid & 1;              // 0..1
    int m0 = blockIdx.y * GBM, n0 = blockIdx.x * GBN;

    wmma::fragment<wmma::accumulator, 16, 16, 8, float> acc[2][2];
#pragma unroll
    for (int i = 0; i < 2; i++)
#pragma unroll
        for (int j = 0; j < 2; j++) wmma::fill_fragment(acc[i][j], 0.f);

    // Global load mapping: per thread, A = two float4 (rows tid>>2 and +64), B = one float4
    int lr = tid >> 2;              // 0..63
    int lc = (tid & 3) * 4;         // 0,4,8,12
    const float* Aptr0 = A + (long)(m0 + lr) * K + lc;
    const float* Aptr1 = Aptr0 + (long)64 * K;
    int nB = n0 + lr;
    const float* Bptr = B + (long)nB * K + lc;
    bool bok = nB < N;
    int sOff = lr * GPAD + lc;

    // stage 0
    {
        float4 a0 = *(const float4*)Aptr0;
        float4 a1 = *(const float4*)Aptr1;
        float4 b  = bok ? *(const float4*)Bptr : make_float4(0.f,0.f,0.f,0.f);
        *(float4*)(As + sOff) = a0;
        *(float4*)(As + 64 * GPAD + sOff) = a1;
        *(float4*)(Bs + sOff) = b;
    }
    __syncthreads();

    int nk = K / GBK;
    for (int kt = 0; kt < nk; kt++) {
        int cur = kt & 1, nxt = cur ^ 1;
        float4 a0, a1, b;
        bool more = (kt + 1 < nk);
        if (more) {
            int koff = (kt + 1) * GBK;
            a0 = *(const float4*)(Aptr0 + koff);
            a1 = *(const float4*)(Aptr1 + koff);
            b  = bok ? *(const float4*)(Bptr + koff) : make_float4(0.f,0.f,0.f,0.f);
        }
        const float* Ac = As + cur * (GBM * GPAD);
        const float* Bc = Bs + cur * (GBN * GPAD);
#pragma unroll
        for (int ks = 0; ks < GBK; ks += 8) {
            wmma::fragment<wmma::matrix_a, 16, 16, 8, wmma::precision::tf32, wmma::row_major> af[2];
            wmma::fragment<wmma::matrix_b, 16, 16, 8, wmma::precision::tf32, wmma::col_major> bf[2];
#pragma unroll
            for (int i = 0; i < 2; i++) {
                wmma::load_matrix_sync(af[i], Ac + (wm * 32 + i * 16) * GPAD + ks, GPAD);
#pragma unroll
                for (int t = 0; t < af[i].num_elements; t++)
                    af[i].x[t] = wmma::__float_to_tf32(af[i].x[t]);
            }
#pragma unroll
            for (int j = 0; j < 2; j++) {
                wmma::load_matrix_sync(bf[j], Bc + (wn * 32 + j * 16) * GPAD + ks, GPAD);
#pragma unroll
                for (int t = 0; t < bf[j].num_elements; t++)
                    bf[j].x[t] = wmma::__float_to_tf32(bf[j].x[t]);
            }
#pragma unroll
            for (int i = 0; i < 2; i++)
#pragma unroll
                for (int j = 0; j < 2; j++)
                    wmma::mma_sync(acc[i][j], af[i], bf[j], acc[i][j]);
        }
        if (more) {
            float* An = As + nxt * (GBM * GPAD);
            float* Bn = Bs + nxt * (GBN * GPAD);
            *(float4*)(An + sOff) = a0;
            *(float4*)(An + 64 * GPAD + sOff) = a1;
            *(float4*)(Bn + sOff) = b;
        }
        __syncthreads();
    }

    // Epilogue: stage through smem (aliases stage buffers; sync above protects)
    float* Ct = sm;                  // 8 warps x 32x36 = 9216 floats
#pragma unroll
    for (int i = 0; i < 2; i++)
#pragma unroll
        for (int j = 0; j < 2; j++)
            wmma::store_matrix_sync(Ct + wid * 1152 + i * 16 * 36 + j * 16,
                                    acc[i][j], 36, wmma::mem_row_major);
    __syncthreads();
    for (int e = tid; e < GBM * GBN; e += 256) {
        int m = e >> 6, n = e & 63;
        int gn = n0 + n;
        if (gn < N) {
            int wmm = m >> 5, wnn = n >> 5;
            float v = Ct[(wmm * 2 + wnn) * 1152 + (m & 31) * 36 + (n & 31)];
            long gi = (long)(m0 + m) * N + gn;
            if (res) v += res[gi];
            C[gi] = v;
        }
    }
}

// ---------------- Causal depthwise conv (width 4) + SiLU ----------------
__global__ void conv_silu_kernel(const float* __restrict__ zx,
                                 const float* __restrict__ cw,
                                 const float* __restrict__ cb,
                                 float* __restrict__ xbc) {
    long idx = (long)blockIdx.x * blockDim.x + threadIdx.x;
    if (idx >= (long)TOK * CONV_DIM) return;
    int c = (int)(idx % CONV_DIM);
    int row = (int)(idx / CONV_DIM);
    int l = row & (SEQLEN - 1);
    int b = row >> 10;
    float v = cb[c];
#pragma unroll
    for (int k = 0; k < D_CONV; k++) {
        int li = l - (D_CONV - 1) + k;
        if (li >= 0)
            v += zx[((long)(b * SEQLEN + li)) * D_IN_PROJ + D_INNER + c] * cw[c * D_CONV + k];
    }
    xbc[idx] = v / (1.f + expf(-v));
}

// ---------------- dt softplus ----------------
__global__ void dt_softplus_kernel(const float* __restrict__ zx,
                                   const float* __restrict__ dt_bias,
                                   float* __restrict__ dtb) {
    int idx = blockIdx.x * blockDim.x + threadIdx.x;
    if (idx >= TOK * NHEADS) return;
    int h = idx & (NHEADS - 1);
    int row = idx >> 5;
    float x = zx[(long)row * D_IN_PROJ + (D_IN_PROJ - NHEADS) + h] + dt_bias[h];
    dtb[idx] = (x > 20.f) ? x : log1pf(expf(x));
}

// ---------------- SSM selective scan: one CTA per (batch, head), 256 threads ----------
// thread -> (p = tid>>2 in 0..63, q = tid&3 -> 32-state slice nb = q*32)
__global__ __launch_bounds__(256, 1)
void scan_kernel(const float* __restrict__ xbc,
                 const float* __restrict__ dtb,
                 const float* __restrict__ A_log,
                 const float* __restrict__ Dp,
                 float* __restrict__ y) {
    int b  = blockIdx.x >> 5;
    int hh = blockIdx.x & 31;
    int tid = threadIdx.x;
    int p = tid >> 2;
    int q = tid & 3;
    int nb = q * 32;
    float A  = -expf(A_log[hh]);
    float Dh = Dp[hh];

    __shared__ float sdt[SEQLEN];
    __shared__ float sdA[SEQLEN];
    __shared__ __align__(16) float sBC[2][256];
    __shared__ __align__(16) float sx[2][64];

    for (int t = tid; t < SEQLEN; t += 256) {
        float dt = dtb[(b * SEQLEN + t) * NHEADS + hh];
        sdt[t] = dt;
        sdA[t] = expf(dt * A);
    }
    // preload t=0
    {
        const float* base0 = xbc + (long)(b * SEQLEN) * CONV_DIM;
        if (tid < 64)
            ((float4*)sBC[0])[tid] = ((const float4*)(base0 + D_INNER))[tid];
        else if (tid < 80)
            ((float4*)sx[0])[tid - 64] = ((const float4*)(base0 + hh * HEADDIM))[tid - 64];
    }
    __syncthreads();

    float hst[32];
#pragma unroll
    for (int i = 0; i < 32; i++) hst[i] = 0.f;

    for (int t = 0; t < SEQLEN; t++) {
        int cur = t & 1, nxt = cur ^ 1;
        if (t + 1 < SEQLEN) {
            const float* baseN = xbc + (long)(b * SEQLEN + t + 1) * CONV_DIM;
            if (tid < 64)
                ((float4*)sBC[nxt])[tid] = ((const float4*)(baseN + D_INNER))[tid];
            else if (tid < 80)
                ((float4*)sx[nxt])[tid - 64] = ((const float4*)(baseN + hh * HEADDIM))[tid - 64];
        }
        float dt = sdt[t], dA = sdA[t];
        float xp = sx[cur][p];
        float coef = dt * xp;
        float acc = 0.f;
        const float4* B4 = (const float4*)(sBC[cur] + nb);
        const float4* C4 = (const float4*)(sBC[cur] + 128 + nb);
#pragma unroll
        for (int i = 0; i < 8; i++) {
            int i2 = (i + 2 * q) & 7;          // bank-conflict-free rotation
            float4 bb = B4[i2];
            float4 cc = C4[i2];
            int s = i2 * 4;
            hst[s+0] = hst[s+0] * dA + coef * bb.x; acc += hst[s+0] * cc.x;
            hst[s+1] = hst[s+1] * dA + coef * bb.y; acc += hst[s+1] * cc.y;
            hst[s+2] = hst[s+2] * dA + coef * bb.z; acc += hst[s+2] * cc.z;
            hst[s+3] = hst[s+3] * dA + coef * bb.w; acc += hst[s+3] * cc.w;
        }
        acc += __shfl_xor_sync(0xffffffffu, acc, 1);
        acc += __shfl_xor_sync(0xffffffffu, acc, 2);
        if (q == 0)
            y[(long)(b * SEQLEN + t) * D_INNER + hh * HEADDIM + p] = acc + Dh * xp;
        __syncthreads();
    }
}

// ---------------- Gated RMSNorm: rmsnorm(y * silu(z)) * w ----------------
__global__ void gated_rmsnorm_kernel(const float* __restrict__ y,
                                     const float* __restrict__ zx,
                                     const float* __restrict__ w,
                                     float* __restrict__ o) {
    int row = blockIdx.x;
    const float* yr = y  + (long)row * D_INNER;
    const float* zr = zx + (long)row * D_IN_PROJ;
    float*       orr = o + (long)row * D_INNER;
    __shared__ float vbuf[D_INNER];
    __shared__ float red[256];
    float s = 0.f;
    for (int c = threadIdx.x; c < D_INNER; c += blockDim.x) {
        float z = zr[c];
        float v = yr[c] * (z / (1.f + expf(-z)));
        vbuf[c] = v;
        s += v * v;
    }
    red[threadIdx.x] = s; __syncthreads();
    for (int st = 128; st > 0; st >>= 1) {
        if (threadIdx.x < st) red[threadIdx.x] += red[threadIdx.x + st];
        __syncthreads();
    }
    float scale = rsqrtf(red[0] / (float)D_INNER + EPS);
    for (int c = threadIdx.x; c < D_INNER; c += blockDim.x)
        orr[c] = vbuf[c] * scale * w[c];
}

// ---------------- SwiGLU combine ----------------
__global__ void swiglu_kernel(const float* __restrict__ g, const float* __restrict__ u,
                              float* __restrict__ o) {
    long idx = (long)blockIdx.x * blockDim.x + threadIdx.x;
    if (idx >= (long)TOK * INTER) return;
    float gv = g[idx];
    o[idx] = (gv / (1.f + expf(-gv))) * u[idx];
}

// ---------------- Launch ----------------
extern "C" void kernel_launch(void* const* d_in, const int* in_sizes, int n_in,
                              void* d_out, int out_size) {
    const float* hidden     = (const float*)d_in[0];
    const float* norm_w     = (const float*)d_in[1];
    const float* in_proj_w  = (const float*)d_in[2];
    const float* conv_w     = (const float*)d_in[3];
    const float* conv_b     = (const float*)d_in[4];
    const float* dt_bias    = (const float*)d_in[5];
    const float* A_log      = (const float*)d_in[6];
    const float* Dp         = (const float*)d_in[7];
    const float* ssm_norm_w = (const float*)d_in[8];
    const float* out_proj_w = (const float*)d_in[9];
    const float* post_norm_w= (const float*)d_in[10];
    const float* gate_w     = (const float*)d_in[11];
    const float* up_w       = (const float*)d_in[12];
    const float* down_w     = (const float*)d_in[13];
    float* out = (float*)d_out;

    float *h, *zx, *xbc, *dtb, *y, *yn, *x1, *h2, *gt, *up, *it;
    cudaGetSymbolAddress((void**)&h,   g_h);
    cudaGetSymbolAddress((void**)&zx,  g_zx);
    cudaGetSymbolAddress((void**)&xbc, g_xbc);
    cudaGetSymbolAddress((void**)&dtb, g_dt);
    cudaGetSymbolAddress((void**)&y,   g_y);
    cudaGetSymbolAddress((void**)&yn,  g_yn);
    cudaGetSymbolAddress((void**)&x1,  g_x1);
    cudaGetSymbolAddress((void**)&h2,  g_h2);
    cudaGetSymbolAddress((void**)&gt,  g_gate);
    cudaGetSymbolAddress((void**)&up,  g_up);
    cudaGetSymbolAddress((void**)&it,  g_inter);

    // 1) pre-norm
    rmsnorm_kernel<<<TOK, 256>>>(hidden, norm_w, h, D_MODEL);

    // 2) in_proj (tf32 tensor cores)
    {
        dim3 grid((D_IN_PROJ + GBN - 1) / GBN, TOK / GBM);
        gemm_tf32<<<grid, 256>>>(h, in_proj_w, nullptr, zx, TOK, D_IN_PROJ, D_MODEL);
    }

    // 3) causal conv + silu
    {
        long total = (long)TOK * CONV_DIM;
        conv_silu_kernel<<<(unsigned)((total + 255) / 256), 256>>>(zx, conv_w, conv_b, xbc);
    }

    // 4) dt softplus
    dt_softplus_kernel<<<(TOK * NHEADS + 255) / 256, 256>>>(zx, dt_bias, dtb);

    // 5) SSM scan
    scan_kernel<<<BATCH * NHEADS, 256>>>(xbc, dtb, A_log, Dp, y);

    // 6) gated rmsnorm
    gated_rmsnorm_kernel<<<TOK, 256>>>(y, zx, ssm_norm_w, yn);

    // 7) out_proj + residual
    {
        dim3 grid(D_MODEL / GBN, TOK / GBM);
        gemm_tf32<<<grid, 256>>>(yn, out_proj_w, hidden, x1, TOK, D_MODEL, D_INNER);
    }

    // 8) post-norm
    rmsnorm_kernel<<<TOK, 256>>>(x1, post_norm_w, h2, D_MODEL);

    // 9) gate & up GEMMs
    {
        dim3 grid(INTER / GBN, TOK / GBM);
        gemm_tf32<<<grid, 256>>>(h2, gate_w, nullptr, gt, TOK, INTER, D_MODEL);
        gemm_tf32<<<grid, 256>>>(h2, up_w,   nullptr, up, TOK, INTER, D_MODEL);
    }

    // 10) swiglu
    {
        long total = (long)TOK * INTER;
        swiglu_kernel<<<(unsigned)((total + 255) / 256), 256>>>(gt, up, it);
    }

    // 11) down proj + residual -> out
    {
        dim3 grid(D_MODEL / GBN, TOK / GBM);
        gemm_tf32<<<grid, 256>>>(it, down_w, x1, out, TOK, D_MODEL, INTER);
    }
}